// round 15
// baseline (speedup 1.0000x reference)
#include <cuda_runtime.h>

// Reverb via four-step FFT convolution — R14 pipeline with single-wave
// inverse-cols kernel (TILE=4, 512 blocks: no wave quantization; input is
// L2-resident). NFFT = 3*2^20 = 768*4096; NH = 768*2048.

#define NFFT   3145728
#define NH     1572864
#define N2     4096
#define N2V    2048
#define TILE   8
#define LOG2TILE 3
#define TILE_V   4
#define LOG2TILE_V 2
#define SMPAD_R  4224
#define SMPAD_R2 2112
#define SMPAD_C  6336
#define SMPAD_CV 3168        // SW(768*4-1)=3166

__device__ float2 g_bufA[1 << 22];
__device__ float2 g_bufB[1 << 22];
__device__ unsigned int g_max_bits;

__device__ __forceinline__ float2 cmul(float2 a, float2 b) {
    return make_float2(fmaf(a.x, b.x, -(a.y * b.y)),
                       fmaf(a.x, b.y,  (a.y * b.x)));
}
__device__ __forceinline__ float2 twid(float ang) {   // e^{-i ang}
    float sn, cs; __sincosf(ang, &sn, &cs);
    return make_float2(cs, -sn);
}
__device__ __forceinline__ int SW(int x) { return x + (x >> 5); }

__device__ __forceinline__ void make_tw8(float2 w1, float2* tw) {
    tw[0] = make_float2(1.0f, 0.0f);
    tw[1] = w1;
    tw[2] = cmul(w1, w1);
    tw[3] = cmul(tw[2], w1);
    tw[4] = cmul(tw[2], tw[2]);
    tw[5] = cmul(tw[4], w1);
    tw[6] = cmul(tw[4], tw[2]);
    tw[7] = cmul(tw[4], tw[3]);
}
__device__ __forceinline__ void make_tw16(float2 w1, float2* tw) {
    tw[0] = make_float2(1.0f, 0.0f);
    tw[1] = w1;
    tw[2] = cmul(w1, w1);
    tw[3] = cmul(tw[2], w1);
    tw[4] = cmul(tw[2], tw[2]);
    tw[8] = cmul(tw[4], tw[4]);
    tw[12] = cmul(tw[8], tw[4]);
    tw[5]  = cmul(tw[4],  w1);
    tw[6]  = cmul(tw[4],  tw[2]);
    tw[7]  = cmul(tw[4],  tw[3]);
    tw[9]  = cmul(tw[8],  w1);
    tw[10] = cmul(tw[8],  tw[2]);
    tw[11] = cmul(tw[8],  tw[3]);
    tw[13] = cmul(tw[12], w1);
    tw[14] = cmul(tw[12], tw[2]);
    tw[15] = cmul(tw[12], tw[3]);
}

__device__ __forceinline__ void r4core(float2 a, float2 b, float2 c, float2 d,
                                       float2& e0, float2& e1, float2& e2, float2& e3) {
    float2 apc = make_float2(a.x + c.x, a.y + c.y);
    float2 amc = make_float2(a.x - c.x, a.y - c.y);
    float2 bpd = make_float2(b.x + d.x, b.y + d.y);
    float2 bmd = make_float2(b.x - d.x, b.y - d.y);
    e0 = make_float2(apc.x + bpd.x, apc.y + bpd.y);
    e1 = make_float2(amc.x + bmd.y, amc.y - bmd.x);
    e2 = make_float2(apc.x - bpd.x, apc.y - bpd.y);
    e3 = make_float2(amc.x - bmd.y, amc.y + bmd.x);
}

__device__ __forceinline__ void dft8(const float2* x, float2* X) {
    const float R2 = 0.70710678118654752440f;
    float2 E0, E1, E2, E3, O0, O1, O2, O3;
    r4core(x[0], x[2], x[4], x[6], E0, E1, E2, E3);
    r4core(x[1], x[3], x[5], x[7], O0, O1, O2, O3);
    float2 T1 = cmul(O1, make_float2( R2, -R2));
    float2 T2 = make_float2(O2.y, -O2.x);
    float2 T3 = cmul(O3, make_float2(-R2, -R2));
    X[0] = make_float2(E0.x + O0.x, E0.y + O0.y);
    X[4] = make_float2(E0.x - O0.x, E0.y - O0.y);
    X[1] = make_float2(E1.x + T1.x, E1.y + T1.y);
    X[5] = make_float2(E1.x - T1.x, E1.y - T1.y);
    X[2] = make_float2(E2.x + T2.x, E2.y + T2.y);
    X[6] = make_float2(E2.x - T2.x, E2.y - T2.y);
    X[3] = make_float2(E3.x + T3.x, E3.y + T3.y);
    X[7] = make_float2(E3.x - T3.x, E3.y - T3.y);
}

__device__ __forceinline__ void dft16(const float2* x, float2* X) {
    const float C1 = 0.92387953251128675613f;
    const float S1 = 0.38268343236508977173f;
    const float R2 = 0.70710678118654752440f;
    float2 t0[4], t1[4], t2[4], t3[4];
    r4core(x[0], x[4], x[8],  x[12], t0[0], t0[1], t0[2], t0[3]);
    r4core(x[1], x[5], x[9],  x[13], t1[0], t1[1], t1[2], t1[3]);
    r4core(x[2], x[6], x[10], x[14], t2[0], t2[1], t2[2], t2[3]);
    r4core(x[3], x[7], x[11], x[15], t3[0], t3[1], t3[2], t3[3]);
    t1[1] = cmul(t1[1], make_float2( C1, -S1));
    t1[2] = cmul(t1[2], make_float2( R2, -R2));
    t1[3] = cmul(t1[3], make_float2( S1, -C1));
    t2[1] = cmul(t2[1], make_float2( R2, -R2));
    t2[2] = make_float2(t2[2].y, -t2[2].x);
    t2[3] = cmul(t2[3], make_float2(-R2, -R2));
    t3[1] = cmul(t3[1], make_float2( S1, -C1));
    t3[2] = cmul(t3[2], make_float2(-R2, -R2));
    t3[3] = cmul(t3[3], make_float2(-C1,  S1));
    r4core(t0[0], t1[0], t2[0], t3[0], X[0], X[4], X[8],  X[12]);
    r4core(t0[1], t1[1], t2[1], t3[1], X[1], X[5], X[9],  X[13]);
    r4core(t0[2], t1[2], t2[2], t3[2], X[2], X[6], X[10], X[14]);
    r4core(t0[3], t1[3], t2[3], t3[3], X[3], X[7], X[11], X[15]);
}

// 12-point DFT, natural-order output.
__device__ __forceinline__ void dft12(const float2* x, float2* X) {
    const float SQ32 = 0.86602540378443864676f;
    float2 T[4][3];
    #pragma unroll
    for (int r = 0; r < 4; r++) {
        float2 a = x[r], b = x[4 + r], c = x[8 + r];
        float2 t = make_float2(b.x + c.x, b.y + c.y);
        float2 u = make_float2(b.x - c.x, b.y - c.y);
        T[r][0] = make_float2(a.x + t.x, a.y + t.y);
        float rx = a.x - 0.5f * t.x, ry = a.y - 0.5f * t.y;
        T[r][1] = make_float2(rx + SQ32 * u.y, ry - SQ32 * u.x);
        T[r][2] = make_float2(rx - SQ32 * u.y, ry + SQ32 * u.x);
    }
    const float2 W1 = make_float2( SQ32, -0.5f );
    const float2 W2 = make_float2( 0.5f, -SQ32 );
    const float2 W4 = make_float2(-0.5f, -SQ32 );
    T[1][1] = cmul(T[1][1], W1);
    T[1][2] = cmul(T[1][2], W2);
    T[2][1] = cmul(T[2][1], W2);
    T[2][2] = cmul(T[2][2], W4);
    T[3][1] = make_float2(T[3][1].y, -T[3][1].x);
    T[3][2] = make_float2(-T[3][2].x, -T[3][2].y);
    #pragma unroll
    for (int k1 = 0; k1 < 3; k1++)
        r4core(T[0][k1], T[1][k1], T[2][k1], T[3][k1],
               X[k1], X[k1 + 3], X[k1 + 6], X[k1 + 9]);
}

__device__ __forceinline__ float2 unpackY(float2 zk, float2 zn) {
    float2 A  = make_float2(0.5f * (zk.x + zn.x), 0.5f * (zk.y - zn.y));
    float2 Dv = make_float2(zk.x - zn.x, zk.y + zn.y);
    float2 H  = make_float2(0.5f * Dv.y, -0.5f * Dv.x);
    return cmul(A, H);
}

__device__ __forceinline__ void c2rsplit(float2 Ym, float2 Yc, float th,
                                         float2& wm, float2& wmir) {
    float2 E = make_float2(0.5f * (Ym.x + Yc.x), 0.5f * (Ym.y - Yc.y));
    float2 G = make_float2(0.5f * (Ym.x - Yc.x), 0.5f * (Ym.y + Yc.y));
    float sn, cs; __sincosf(th, &sn, &cs);
    float2 O = cmul(make_float2(cs, sn), G);
    wm   = make_float2(E.x - O.y, -E.y - O.x);
    wmir = make_float2(E.x + O.y,  E.y - O.x);
}

#define EL(idx, b)  SW((((idx) << LOG2TILE)) + (b))
#define ELV(idx, b) SW((((idx) << LOG2TILE_V)) + (b))

// ---------------- fwd_cols768 (R10 form): radices 16/16/3, 384 threads
__global__ void fwd_cols768(const float* __restrict__ audio, int N,
                            const float* __restrict__ ir, int M,
                            float2* __restrict__ G) {
    extern __shared__ float2 bA[];
    int k20 = blockIdx.x * TILE;
    int t = threadIdx.x;
    int b = t & (TILE - 1), tt = t >> LOG2TILE;    // tt in [0,48)
    if (blockIdx.x == 0 && t == 0) g_max_bits = 0u;
    float2 x[16], X[16], tw[16];

    #pragma unroll
    for (int u = 0; u < 16; u++) {
        int n = (tt + 48 * u) * 4096 + k20 + b;
        float re = (n < N) ? audio[n] : 0.0f;
        float im = (n < M) ? ir[M - 1 - n] : 0.0f;
        x[u] = make_float2(re, im);
    }
    dft16(x, X);
    make_tw16(twid((6.2831853071795865f / 768.0f) * (float)tt), tw);
    #pragma unroll
    for (int r = 0; r < 16; r++)
        bA[SW(((16 * tt + r) << LOG2TILE) + b)] = (r == 0) ? X[0] : cmul(X[r], tw[r]);
    __syncthreads();

    #pragma unroll
    for (int u = 0; u < 16; u++) x[u] = bA[SW(((tt + 48 * u) << LOG2TILE) + b)];
    __syncthreads();
    dft16(x, X);
    {
        int q = tt & 15, p = tt >> 4;
        make_tw16(twid((6.2831853071795865f / 48.0f) * (float)p), tw);
        int base = q + (p << 8);
        #pragma unroll
        for (int r = 0; r < 16; r++)
            bA[SW(((base + 16 * r) << LOG2TILE) + b)] = (r == 0) ? X[0] : cmul(X[r], tw[r]);
    }
    __syncthreads();

    const float SQ32 = 0.86602540378443864676f;
    const float c0 = 6.2831853071795865f / (float)NFFT;
    int kc = k20 + b;
    float2 cur = twid(c0 * (float)(kc * tt));
    float2 S   = twid(c0 * (float)(kc * 48));
    float2 P1  = twid(c0 * (float)(kc * 256));
    float2 P2  = cmul(P1, P1);
    for (int q = tt; q < 256; q += 48) {
        float2 a  = bA[SW(((q      ) << LOG2TILE) + b)];
        float2 bb = bA[SW(((q + 256) << LOG2TILE) + b)];
        float2 c  = bA[SW(((q + 512) << LOG2TILE) + b)];
        float2 ts = make_float2(bb.x + c.x, bb.y + c.y);
        float2 u  = make_float2(bb.x - c.x, bb.y - c.y);
        float2 e0 = make_float2(a.x + ts.x, a.y + ts.y);
        float rx = a.x - 0.5f * ts.x, ry = a.y - 0.5f * ts.y;
        float2 e1 = make_float2(rx + SQ32 * u.y, ry - SQ32 * u.x);
        float2 e2 = make_float2(rx - SQ32 * u.y, ry + SQ32 * u.x);
        G[(size_t)(q      ) * N2 + kc] = cmul(e0, cur);
        G[(size_t)(q + 256) * N2 + kc] = cmul(e1, cmul(cur, P1));
        G[(size_t)(q + 512) * N2 + kc] = cmul(e2, cmul(cur, P2));
        cur = cmul(cur, S);
    }
}

// ---------------- fwd_rows4096 (R10 form)
__global__ void fwd_rows4096(const float2* __restrict__ in, float2* __restrict__ out) {
    extern __shared__ float2 bA[];
    int t = threadIdx.x;
    const float2* row = in + (size_t)blockIdx.x * N2;
    float2* orow = out + (size_t)blockIdx.x * N2;
    float2 x[16], X[16], tw[16];

    #pragma unroll
    for (int u = 0; u < 16; u++) x[u] = row[t + (u << 8)];
    dft16(x, X);
    make_tw16(twid((6.2831853071795865f / 4096.0f) * (float)t), tw);
    #pragma unroll
    for (int r = 0; r < 16; r++)
        bA[SW(16 * t + r)] = (r == 0) ? X[0] : cmul(X[r], tw[r]);
    __syncthreads();

    #pragma unroll
    for (int u = 0; u < 16; u++) x[u] = bA[SW(t + (u << 8))];
    __syncthreads();
    dft16(x, X);
    {
        int q = t & 15, p = t >> 4;
        make_tw16(twid((6.2831853071795865f / 256.0f) * (float)p), tw);
        int base = q + (p << 8);
        #pragma unroll
        for (int r = 0; r < 16; r++)
            bA[SW(base + 16 * r)] = (r == 0) ? X[0] : cmul(X[r], tw[r]);
    }
    __syncthreads();

    #pragma unroll
    for (int u = 0; u < 16; u++) x[u] = bA[SW(t + (u << 8))];
    dft16(x, X);
    #pragma unroll
    for (int r = 0; r < 16; r++) orow[t + (r << 8)] = X[r];
}

// ---------------- spec_invrows (R10 form): 256 threads, two 128-thr groups
__global__ void spec_invrows(const float2* __restrict__ Zr, float2* __restrict__ H) {
    extern __shared__ float2 sm[];
    float2* win[2] = { sm, sm + SMPAD_R2 };
    int t = threadIdx.x;
    int r = blockIdx.x;
    const float c1 = 6.2831853071795865f / (float)NFFT;

    int row0, row1;
    if (r == 0) {
        row0 = 0; row1 = 384;
        #pragma unroll
        for (int j = 0; j < 4; j++) {
            int c = 1 + t + (j << 8);          // [1,1024]
            float2 Ym = unpackY(Zr[c], Zr[4096 - c]);
            float2 Yc = unpackY(Zr[2048 - c], Zr[2048 + c]);
            float2 wm, wmir;
            c2rsplit(Ym, Yc, c1 * (float)(768 * c), wm, wmir);
            win[0][SW(c)] = wm;
            win[0][SW(2048 - c)] = wmir;
        }
        const size_t base = (size_t)384 * N2;
        #pragma unroll
        for (int j = 0; j < 4; j++) {
            int c = t + (j << 8);              // [0,1023]
            float2 Ym = unpackY(Zr[base + c], Zr[base + 4095 - c]);
            float2 Yc = unpackY(Zr[base + 2047 - c], Zr[base + 2048 + c]);
            float2 wm, wmir;
            c2rsplit(Ym, Yc, c1 * (float)(384 + 768 * c), wm, wmir);
            win[1][SW(c)] = wm;
            win[1][SW(2047 - c)] = wmir;
        }
        if (t == 0) {
            float2 z0 = Zr[0], zh = Zr[2048];
            float Y0 = z0.x * z0.y;
            float Yh = zh.x * zh.y;
            win[0][SW(0)] = make_float2(0.5f * (Y0 + Yh), -0.5f * (Y0 - Yh));
        }
    } else {
        row0 = r; row1 = 768 - r;
        const size_t bR = (size_t)r * N2;
        const size_t bM = (size_t)(768 - r) * N2;
        #pragma unroll
        for (int j = 0; j < 8; j++) {
            int c = t + (j << 8);              // [0,2048)
            float2 Ym = unpackY(Zr[bR + c],        Zr[bM + 4095 - c]);
            float2 Yc = unpackY(Zr[bM + 2047 - c], Zr[bR + 2048 + c]);
            float2 wm, wmir;
            c2rsplit(Ym, Yc, c1 * (float)(r + 768 * c), wm, wmir);
            win[0][SW(c)] = wm;
            win[1][SW(2047 - c)] = wmir;
        }
    }
    __syncthreads();

    int g = t >> 7;
    int tl = t & 127;
    int n1 = g ? row1 : row0;
    float2* wi = win[g];
    float2* orow = H + (size_t)n1 * N2V;
    float2 x[16], X[16], tw[16];

    #pragma unroll
    for (int u = 0; u < 16; u++) x[u] = wi[SW(tl + (u << 7))];
    __syncthreads();
    dft16(x, X);
    make_tw16(twid((6.2831853071795865f / 2048.0f) * (float)tl), tw);
    #pragma unroll
    for (int rr = 0; rr < 16; rr++)
        wi[SW(16 * tl + rr)] = (rr == 0) ? X[0] : cmul(X[rr], tw[rr]);
    __syncthreads();

    #pragma unroll
    for (int u = 0; u < 16; u++) x[u] = wi[SW(tl + (u << 7))];
    __syncthreads();
    dft16(x, X);
    {
        int q = tl & 15, p = tl >> 4;
        make_tw16(twid((6.2831853071795865f / 128.0f) * (float)p), tw);
        int base = q + (p << 8);
        #pragma unroll
        for (int rr = 0; rr < 16; rr++)
            wi[SW(base + 16 * rr)] = (rr == 0) ? X[0] : cmul(X[rr], tw[rr]);
    }
    __syncthreads();

    {
        const float c0 = 6.2831853071795865f / (float)NH;
        float2 y[8], Y8[8];
        #pragma unroll
        for (int qq0 = 0; qq0 < 2; qq0++) {
            int q = tl + (qq0 << 7);
            #pragma unroll
            for (int u = 0; u < 8; u++) y[u] = wi[SW(q + (u << 8))];
            dft8(y, Y8);
            float2 V  = twid(c0 * (float)(n1 << 8));
            float2 V2 = cmul(V, V);
            float2 V4 = cmul(V2, V2);
            float2 base0 = twid(c0 * (float)(n1 * q));
            float2 vv[8];
            vv[0] = base0;
            vv[1] = cmul(base0, V);
            vv[2] = cmul(base0, V2);
            vv[3] = cmul(vv[2], V);
            vv[4] = cmul(base0, V4);
            vv[5] = cmul(vv[4], V);
            vv[6] = cmul(vv[4], V2);
            vv[7] = cmul(vv[6], V);
            #pragma unroll
            for (int rr = 0; rr < 8; rr++) orow[q + (rr << 8)] = cmul(Y8[rr], vv[rr]);
        }
    }
}

// ---------------- fft_cols768v: radices (8,8,12), TILE_V=4, 384 threads,
// 512 blocks (single wave). Windowed y pairs (Re,-Im) + fused max-abs.
__global__ void fft_cols768v(const float2* __restrict__ in, float2* __restrict__ outv,
                             int lo, int hi) {
    extern __shared__ float2 bA[];
    int k20 = blockIdx.x * TILE_V;
    int t = threadIdx.x;
    int b = t & (TILE_V - 1), tg = t >> LOG2TILE_V;   // tg in [0,96)
    float2 x[8], X[8], tw[8];

    // stage 1: radix-8, p=tg
    #pragma unroll
    for (int u = 0; u < 8; u++)
        x[u] = in[(size_t)(tg + 96 * u) * N2V + k20 + b];
    dft8(x, X);
    make_tw8(twid((6.2831853071795865f / 768.0f) * (float)tg), tw);
    #pragma unroll
    for (int r = 0; r < 8; r++)
        bA[ELV(8 * tg + r, b)] = (r == 0) ? X[0] : cmul(X[r], tw[r]);
    __syncthreads();

    // stage 2: radix-8, n=96, s=8; q=tg&7, p=tg>>3, in-place
    {
        int q = tg & 7, p = tg >> 3;
        #pragma unroll
        for (int u = 0; u < 8; u++) x[u] = bA[ELV(q + 8 * p + 96 * u, b)];
        __syncthreads();
        dft8(x, X);
        make_tw8(twid((6.2831853071795865f / 96.0f) * (float)p), tw);
        #pragma unroll
        for (int r = 0; r < 8; r++)
            bA[ELV(q + 64 * p + 8 * r, b)] = (r == 0) ? X[0] : cmul(X[r], tw[r]);
    }
    __syncthreads();

    // stage 3: radix-12, p=0; tg<64 active; windowed store + max
    float lmax = 0.0f;
    if (tg < 64) {
        float2 y[12], Y[12];
        int q = tg;
        #pragma unroll
        for (int u = 0; u < 12; u++) y[u] = bA[ELV(q + 64 * u, b)];
        dft12(y, Y);
        int kc = k20 + b;
        unsigned wlen = (unsigned)(hi - lo);
        #pragma unroll
        for (int k = 0; k < 12; k++) {
            int k1 = q + 64 * k;
            int m = kc + (k1 << 11);
            int j0 = 2 * m;
            float2 v = make_float2(Y[k].x, -Y[k].y);
            if (j0 + 1 >= lo && j0 < hi) outv[m] = v;
            if ((unsigned)(j0     - lo) < wlen) lmax = fmaxf(lmax, fabsf(v.x));
            if ((unsigned)(j0 + 1 - lo) < wlen) lmax = fmaxf(lmax, fabsf(v.y));
        }
    }
    #pragma unroll
    for (int off = 16; off > 0; off >>= 1)
        lmax = fmaxf(lmax, __shfl_xor_sync(0xffffffffu, lmax, off));
    __shared__ float wmax[12];
    int lane = t & 31, w = t >> 5;
    if (lane == 0) wmax[w] = lmax;
    __syncthreads();
    if (t == 0) {
        float mx = wmax[0];
        #pragma unroll
        for (int j = 1; j < 12; j++) mx = fmaxf(mx, wmax[j]);
        atomicMax(&g_max_bits, __float_as_uint(mx));   // values >= 0
    }
}

// ---------------- final: out[i] = y[M-1+i] * (1/max), float4 stores
__global__ void final_kernel(const float* __restrict__ yf,
                             float* __restrict__ out, int N, int M) {
    int i4 = (blockIdx.x * blockDim.x + threadIdx.x) << 2;
    if (i4 >= N) return;
    float inv = 1.0f / __uint_as_float(g_max_bits);
    const float* src = yf + (M - 1) + i4;
    if (i4 + 3 < N) {
        float4 v;
        v.x = src[0] * inv;
        v.y = src[1] * inv;
        v.z = src[2] * inv;
        v.w = src[3] * inv;
        *reinterpret_cast<float4*>(out + i4) = v;
    } else {
        for (int j = 0; i4 + j < N; j++) out[i4 + j] = src[j] * inv;
    }
}

extern "C" void kernel_launch(void* const* d_in, const int* in_sizes, int n_in,
                              void* d_out, int out_size) {
    const float* audio = (const float*)d_in[0];
    const float* ir    = (const float*)d_in[1];
    const int N = in_sizes[0];
    const int M = in_sizes[1];
    float* out = (float*)d_out;

    float2 *A = nullptr, *B = nullptr;
    cudaGetSymbolAddress((void**)&A, g_bufA);
    cudaGetSymbolAddress((void**)&B, g_bufB);

    const int SMEM_R  = SMPAD_R  * (int)sizeof(float2);      // 33792
    const int SMEM_C  = SMPAD_C  * (int)sizeof(float2);      // 50688
    const int SMEM_SI = 2 * SMPAD_R2 * (int)sizeof(float2);  // 33792
    const int SMEM_CV = SMPAD_CV * (int)sizeof(float2);      // 25344
    cudaFuncSetAttribute(fwd_cols768,  cudaFuncAttributeMaxDynamicSharedMemorySize, SMEM_C);
    cudaFuncSetAttribute(fwd_rows4096, cudaFuncAttributeMaxDynamicSharedMemorySize, SMEM_R);
    cudaFuncSetAttribute(spec_invrows, cudaFuncAttributeMaxDynamicSharedMemorySize, SMEM_SI);
    cudaFuncSetAttribute(fft_cols768v, cudaFuncAttributeMaxDynamicSharedMemorySize, SMEM_CV);

    // forward: cols (direct input, pack fused) -> A (G), rows A -> B (Zrow)
    fwd_cols768<<<N2 / TILE, 384, SMEM_C>>>(audio, N, ir, M, A);
    fwd_rows4096<<<768, 256, SMEM_R>>>(A, B);

    // fused specmul + C2R + inverse row FFTs: B (Zrow) -> A (H)
    spec_invrows<<<384, 256, SMEM_SI>>>(B, A);

    // inverse cols (single wave, 512 blocks): A -> B (y pairs + fused max)
    fft_cols768v<<<N2V / TILE_V, 384, SMEM_CV>>>(A, B, M - 1, M - 1 + N);

    final_kernel<<<(N / 4 + 255) / 256, 256>>>((const float*)B, out, N, M);
}

// round 16
// speedup vs baseline: 1.0007x; 1.0007x over previous
#include <cuda_runtime.h>

// Reverb via four-step FFT convolution — R14 best-measured pipeline with a
// branch-free interior fast path in the inverse-cols epilogue.
// NFFT = 3*2^20 = 768*4096; NH = 768*2048.

#define NFFT   3145728
#define NH     1572864
#define N2     4096
#define N2V    2048
#define TILE   8
#define LOG2TILE 3
#define SMPAD_R  4224
#define SMPAD_R2 2112
#define SMPAD_C  6336

__device__ float2 g_bufA[1 << 22];
__device__ float2 g_bufB[1 << 22];
__device__ unsigned int g_max_bits;

__device__ __forceinline__ float2 cmul(float2 a, float2 b) {
    return make_float2(fmaf(a.x, b.x, -(a.y * b.y)),
                       fmaf(a.x, b.y,  (a.y * b.x)));
}
__device__ __forceinline__ float2 twid(float ang) {   // e^{-i ang}
    float sn, cs; __sincosf(ang, &sn, &cs);
    return make_float2(cs, -sn);
}
__device__ __forceinline__ int SW(int x) { return x + (x >> 5); }

__device__ __forceinline__ void make_tw8(float2 w1, float2* tw) {
    tw[0] = make_float2(1.0f, 0.0f);
    tw[1] = w1;
    tw[2] = cmul(w1, w1);
    tw[3] = cmul(tw[2], w1);
    tw[4] = cmul(tw[2], tw[2]);
    tw[5] = cmul(tw[4], w1);
    tw[6] = cmul(tw[4], tw[2]);
    tw[7] = cmul(tw[4], tw[3]);
}
__device__ __forceinline__ void make_tw16(float2 w1, float2* tw) {
    tw[0] = make_float2(1.0f, 0.0f);
    tw[1] = w1;
    tw[2] = cmul(w1, w1);
    tw[3] = cmul(tw[2], w1);
    tw[4] = cmul(tw[2], tw[2]);
    tw[8] = cmul(tw[4], tw[4]);
    tw[12] = cmul(tw[8], tw[4]);
    tw[5]  = cmul(tw[4],  w1);
    tw[6]  = cmul(tw[4],  tw[2]);
    tw[7]  = cmul(tw[4],  tw[3]);
    tw[9]  = cmul(tw[8],  w1);
    tw[10] = cmul(tw[8],  tw[2]);
    tw[11] = cmul(tw[8],  tw[3]);
    tw[13] = cmul(tw[12], w1);
    tw[14] = cmul(tw[12], tw[2]);
    tw[15] = cmul(tw[12], tw[3]);
}

__device__ __forceinline__ void r4core(float2 a, float2 b, float2 c, float2 d,
                                       float2& e0, float2& e1, float2& e2, float2& e3) {
    float2 apc = make_float2(a.x + c.x, a.y + c.y);
    float2 amc = make_float2(a.x - c.x, a.y - c.y);
    float2 bpd = make_float2(b.x + d.x, b.y + d.y);
    float2 bmd = make_float2(b.x - d.x, b.y - d.y);
    e0 = make_float2(apc.x + bpd.x, apc.y + bpd.y);
    e1 = make_float2(amc.x + bmd.y, amc.y - bmd.x);
    e2 = make_float2(apc.x - bpd.x, apc.y - bpd.y);
    e3 = make_float2(amc.x - bmd.y, amc.y + bmd.x);
}

__device__ __forceinline__ void dft8(const float2* x, float2* X) {
    const float R2 = 0.70710678118654752440f;
    float2 E0, E1, E2, E3, O0, O1, O2, O3;
    r4core(x[0], x[2], x[4], x[6], E0, E1, E2, E3);
    r4core(x[1], x[3], x[5], x[7], O0, O1, O2, O3);
    float2 T1 = cmul(O1, make_float2( R2, -R2));
    float2 T2 = make_float2(O2.y, -O2.x);
    float2 T3 = cmul(O3, make_float2(-R2, -R2));
    X[0] = make_float2(E0.x + O0.x, E0.y + O0.y);
    X[4] = make_float2(E0.x - O0.x, E0.y - O0.y);
    X[1] = make_float2(E1.x + T1.x, E1.y + T1.y);
    X[5] = make_float2(E1.x - T1.x, E1.y - T1.y);
    X[2] = make_float2(E2.x + T2.x, E2.y + T2.y);
    X[6] = make_float2(E2.x - T2.x, E2.y - T2.y);
    X[3] = make_float2(E3.x + T3.x, E3.y + T3.y);
    X[7] = make_float2(E3.x - T3.x, E3.y - T3.y);
}

__device__ __forceinline__ void dft16(const float2* x, float2* X) {
    const float C1 = 0.92387953251128675613f;
    const float S1 = 0.38268343236508977173f;
    const float R2 = 0.70710678118654752440f;
    float2 t0[4], t1[4], t2[4], t3[4];
    r4core(x[0], x[4], x[8],  x[12], t0[0], t0[1], t0[2], t0[3]);
    r4core(x[1], x[5], x[9],  x[13], t1[0], t1[1], t1[2], t1[3]);
    r4core(x[2], x[6], x[10], x[14], t2[0], t2[1], t2[2], t2[3]);
    r4core(x[3], x[7], x[11], x[15], t3[0], t3[1], t3[2], t3[3]);
    t1[1] = cmul(t1[1], make_float2( C1, -S1));
    t1[2] = cmul(t1[2], make_float2( R2, -R2));
    t1[3] = cmul(t1[3], make_float2( S1, -C1));
    t2[1] = cmul(t2[1], make_float2( R2, -R2));
    t2[2] = make_float2(t2[2].y, -t2[2].x);
    t2[3] = cmul(t2[3], make_float2(-R2, -R2));
    t3[1] = cmul(t3[1], make_float2( S1, -C1));
    t3[2] = cmul(t3[2], make_float2(-R2, -R2));
    t3[3] = cmul(t3[3], make_float2(-C1,  S1));
    r4core(t0[0], t1[0], t2[0], t3[0], X[0], X[4], X[8],  X[12]);
    r4core(t0[1], t1[1], t2[1], t3[1], X[1], X[5], X[9],  X[13]);
    r4core(t0[2], t1[2], t2[2], t3[2], X[2], X[6], X[10], X[14]);
    r4core(t0[3], t1[3], t2[3], t3[3], X[3], X[7], X[11], X[15]);
}

// 12-point DFT, natural-order output.
__device__ __forceinline__ void dft12(const float2* x, float2* X) {
    const float SQ32 = 0.86602540378443864676f;
    float2 T[4][3];
    #pragma unroll
    for (int r = 0; r < 4; r++) {
        float2 a = x[r], b = x[4 + r], c = x[8 + r];
        float2 t = make_float2(b.x + c.x, b.y + c.y);
        float2 u = make_float2(b.x - c.x, b.y - c.y);
        T[r][0] = make_float2(a.x + t.x, a.y + t.y);
        float rx = a.x - 0.5f * t.x, ry = a.y - 0.5f * t.y;
        T[r][1] = make_float2(rx + SQ32 * u.y, ry - SQ32 * u.x);
        T[r][2] = make_float2(rx - SQ32 * u.y, ry + SQ32 * u.x);
    }
    const float2 W1 = make_float2( SQ32, -0.5f );
    const float2 W2 = make_float2( 0.5f, -SQ32 );
    const float2 W4 = make_float2(-0.5f, -SQ32 );
    T[1][1] = cmul(T[1][1], W1);
    T[1][2] = cmul(T[1][2], W2);
    T[2][1] = cmul(T[2][1], W2);
    T[2][2] = cmul(T[2][2], W4);
    T[3][1] = make_float2(T[3][1].y, -T[3][1].x);
    T[3][2] = make_float2(-T[3][2].x, -T[3][2].y);
    #pragma unroll
    for (int k1 = 0; k1 < 3; k1++)
        r4core(T[0][k1], T[1][k1], T[2][k1], T[3][k1],
               X[k1], X[k1 + 3], X[k1 + 6], X[k1 + 9]);
}

__device__ __forceinline__ float2 unpackY(float2 zk, float2 zn) {
    float2 A  = make_float2(0.5f * (zk.x + zn.x), 0.5f * (zk.y - zn.y));
    float2 Dv = make_float2(zk.x - zn.x, zk.y + zn.y);
    float2 H  = make_float2(0.5f * Dv.y, -0.5f * Dv.x);
    return cmul(A, H);
}

__device__ __forceinline__ void c2rsplit(float2 Ym, float2 Yc, float th,
                                         float2& wm, float2& wmir) {
    float2 E = make_float2(0.5f * (Ym.x + Yc.x), 0.5f * (Ym.y - Yc.y));
    float2 G = make_float2(0.5f * (Ym.x - Yc.x), 0.5f * (Ym.y + Yc.y));
    float sn, cs; __sincosf(th, &sn, &cs);
    float2 O = cmul(make_float2(cs, sn), G);
    wm   = make_float2(E.x - O.y, -E.y - O.x);
    wmir = make_float2(E.x + O.y,  E.y - O.x);
}

#define EL(idx, b) SW((((idx) << LOG2TILE)) + (b))

// ---------------- fwd_cols768: radices 16/16/3, 384 threads, TILE=8
__global__ void fwd_cols768(const float* __restrict__ audio, int N,
                            const float* __restrict__ ir, int M,
                            float2* __restrict__ G) {
    extern __shared__ float2 bA[];
    int k20 = blockIdx.x * TILE;
    int t = threadIdx.x;
    int b = t & (TILE - 1), tt = t >> LOG2TILE;    // tt in [0,48)
    if (blockIdx.x == 0 && t == 0) g_max_bits = 0u;
    float2 x[16], X[16], tw[16];

    #pragma unroll
    for (int u = 0; u < 16; u++) {
        int n = (tt + 48 * u) * 4096 + k20 + b;
        float re = (n < N) ? audio[n] : 0.0f;
        float im = (n < M) ? ir[M - 1 - n] : 0.0f;
        x[u] = make_float2(re, im);
    }
    dft16(x, X);
    make_tw16(twid((6.2831853071795865f / 768.0f) * (float)tt), tw);
    #pragma unroll
    for (int r = 0; r < 16; r++)
        bA[SW(((16 * tt + r) << LOG2TILE) + b)] = (r == 0) ? X[0] : cmul(X[r], tw[r]);
    __syncthreads();

    #pragma unroll
    for (int u = 0; u < 16; u++) x[u] = bA[SW(((tt + 48 * u) << LOG2TILE) + b)];
    __syncthreads();
    dft16(x, X);
    {
        int q = tt & 15, p = tt >> 4;
        make_tw16(twid((6.2831853071795865f / 48.0f) * (float)p), tw);
        int base = q + (p << 8);
        #pragma unroll
        for (int r = 0; r < 16; r++)
            bA[SW(((base + 16 * r) << LOG2TILE) + b)] = (r == 0) ? X[0] : cmul(X[r], tw[r]);
    }
    __syncthreads();

    const float SQ32 = 0.86602540378443864676f;
    const float c0 = 6.2831853071795865f / (float)NFFT;
    int kc = k20 + b;
    float2 cur = twid(c0 * (float)(kc * tt));
    float2 S   = twid(c0 * (float)(kc * 48));
    float2 P1  = twid(c0 * (float)(kc * 256));
    float2 P2  = cmul(P1, P1);
    for (int q = tt; q < 256; q += 48) {
        float2 a  = bA[SW(((q      ) << LOG2TILE) + b)];
        float2 bb = bA[SW(((q + 256) << LOG2TILE) + b)];
        float2 c  = bA[SW(((q + 512) << LOG2TILE) + b)];
        float2 ts = make_float2(bb.x + c.x, bb.y + c.y);
        float2 u  = make_float2(bb.x - c.x, bb.y - c.y);
        float2 e0 = make_float2(a.x + ts.x, a.y + ts.y);
        float rx = a.x - 0.5f * ts.x, ry = a.y - 0.5f * ts.y;
        float2 e1 = make_float2(rx + SQ32 * u.y, ry - SQ32 * u.x);
        float2 e2 = make_float2(rx - SQ32 * u.y, ry + SQ32 * u.x);
        G[(size_t)(q      ) * N2 + kc] = cmul(e0, cur);
        G[(size_t)(q + 256) * N2 + kc] = cmul(e1, cmul(cur, P1));
        G[(size_t)(q + 512) * N2 + kc] = cmul(e2, cmul(cur, P2));
        cur = cmul(cur, S);
    }
}

// ---------------- fwd_rows4096
__global__ void fwd_rows4096(const float2* __restrict__ in, float2* __restrict__ out) {
    extern __shared__ float2 bA[];
    int t = threadIdx.x;
    const float2* row = in + (size_t)blockIdx.x * N2;
    float2* orow = out + (size_t)blockIdx.x * N2;
    float2 x[16], X[16], tw[16];

    #pragma unroll
    for (int u = 0; u < 16; u++) x[u] = row[t + (u << 8)];
    dft16(x, X);
    make_tw16(twid((6.2831853071795865f / 4096.0f) * (float)t), tw);
    #pragma unroll
    for (int r = 0; r < 16; r++)
        bA[SW(16 * t + r)] = (r == 0) ? X[0] : cmul(X[r], tw[r]);
    __syncthreads();

    #pragma unroll
    for (int u = 0; u < 16; u++) x[u] = bA[SW(t + (u << 8))];
    __syncthreads();
    dft16(x, X);
    {
        int q = t & 15, p = t >> 4;
        make_tw16(twid((6.2831853071795865f / 256.0f) * (float)p), tw);
        int base = q + (p << 8);
        #pragma unroll
        for (int r = 0; r < 16; r++)
            bA[SW(base + 16 * r)] = (r == 0) ? X[0] : cmul(X[r], tw[r]);
    }
    __syncthreads();

    #pragma unroll
    for (int u = 0; u < 16; u++) x[u] = bA[SW(t + (u << 8))];
    dft16(x, X);
    #pragma unroll
    for (int r = 0; r < 16; r++) orow[t + (r << 8)] = X[r];
}

// ---------------- spec_invrows: 256 threads, two 128-thr groups
__global__ void spec_invrows(const float2* __restrict__ Zr, float2* __restrict__ H) {
    extern __shared__ float2 sm[];
    float2* win[2] = { sm, sm + SMPAD_R2 };
    int t = threadIdx.x;
    int r = blockIdx.x;
    const float c1 = 6.2831853071795865f / (float)NFFT;

    int row0, row1;
    if (r == 0) {
        row0 = 0; row1 = 384;
        #pragma unroll
        for (int j = 0; j < 4; j++) {
            int c = 1 + t + (j << 8);          // [1,1024]
            float2 Ym = unpackY(Zr[c], Zr[4096 - c]);
            float2 Yc = unpackY(Zr[2048 - c], Zr[2048 + c]);
            float2 wm, wmir;
            c2rsplit(Ym, Yc, c1 * (float)(768 * c), wm, wmir);
            win[0][SW(c)] = wm;
            win[0][SW(2048 - c)] = wmir;
        }
        const size_t base = (size_t)384 * N2;
        #pragma unroll
        for (int j = 0; j < 4; j++) {
            int c = t + (j << 8);              // [0,1023]
            float2 Ym = unpackY(Zr[base + c], Zr[base + 4095 - c]);
            float2 Yc = unpackY(Zr[base + 2047 - c], Zr[base + 2048 + c]);
            float2 wm, wmir;
            c2rsplit(Ym, Yc, c1 * (float)(384 + 768 * c), wm, wmir);
            win[1][SW(c)] = wm;
            win[1][SW(2047 - c)] = wmir;
        }
        if (t == 0) {
            float2 z0 = Zr[0], zh = Zr[2048];
            float Y0 = z0.x * z0.y;
            float Yh = zh.x * zh.y;
            win[0][SW(0)] = make_float2(0.5f * (Y0 + Yh), -0.5f * (Y0 - Yh));
        }
    } else {
        row0 = r; row1 = 768 - r;
        const size_t bR = (size_t)r * N2;
        const size_t bM = (size_t)(768 - r) * N2;
        #pragma unroll
        for (int j = 0; j < 8; j++) {
            int c = t + (j << 8);              // [0,2048)
            float2 Ym = unpackY(Zr[bR + c],        Zr[bM + 4095 - c]);
            float2 Yc = unpackY(Zr[bM + 2047 - c], Zr[bR + 2048 + c]);
            float2 wm, wmir;
            c2rsplit(Ym, Yc, c1 * (float)(r + 768 * c), wm, wmir);
            win[0][SW(c)] = wm;
            win[1][SW(2047 - c)] = wmir;
        }
    }
    __syncthreads();

    int g = t >> 7;
    int tl = t & 127;
    int n1 = g ? row1 : row0;
    float2* wi = win[g];
    float2* orow = H + (size_t)n1 * N2V;
    float2 x[16], X[16], tw[16];

    #pragma unroll
    for (int u = 0; u < 16; u++) x[u] = wi[SW(tl + (u << 7))];
    __syncthreads();
    dft16(x, X);
    make_tw16(twid((6.2831853071795865f / 2048.0f) * (float)tl), tw);
    #pragma unroll
    for (int rr = 0; rr < 16; rr++)
        wi[SW(16 * tl + rr)] = (rr == 0) ? X[0] : cmul(X[rr], tw[rr]);
    __syncthreads();

    #pragma unroll
    for (int u = 0; u < 16; u++) x[u] = wi[SW(tl + (u << 7))];
    __syncthreads();
    dft16(x, X);
    {
        int q = tl & 15, p = tl >> 4;
        make_tw16(twid((6.2831853071795865f / 128.0f) * (float)p), tw);
        int base = q + (p << 8);
        #pragma unroll
        for (int rr = 0; rr < 16; rr++)
            wi[SW(base + 16 * rr)] = (rr == 0) ? X[0] : cmul(X[rr], tw[rr]);
    }
    __syncthreads();

    {
        const float c0 = 6.2831853071795865f / (float)NH;
        float2 y[8], Y8[8];
        #pragma unroll
        for (int qq0 = 0; qq0 < 2; qq0++) {
            int q = tl + (qq0 << 7);
            #pragma unroll
            for (int u = 0; u < 8; u++) y[u] = wi[SW(q + (u << 8))];
            dft8(y, Y8);
            float2 V  = twid(c0 * (float)(n1 << 8));
            float2 V2 = cmul(V, V);
            float2 V4 = cmul(V2, V2);
            float2 base0 = twid(c0 * (float)(n1 * q));
            float2 vv[8];
            vv[0] = base0;
            vv[1] = cmul(base0, V);
            vv[2] = cmul(base0, V2);
            vv[3] = cmul(vv[2], V);
            vv[4] = cmul(base0, V4);
            vv[5] = cmul(vv[4], V);
            vv[6] = cmul(vv[4], V2);
            vv[7] = cmul(vv[6], V);
            #pragma unroll
            for (int rr = 0; rr < 8; rr++) orow[q + (rr << 8)] = cmul(Y8[rr], vv[rr]);
        }
    }
}

// ---------------- fft_cols768v: radices (8,8,12), 768 threads, TILE=8,
// interior fast path: per-k1 row test replaces per-element window compares.
__global__ void fft_cols768v(const float2* __restrict__ in, float2* __restrict__ outv,
                             int lo, int hi) {
    extern __shared__ float2 bA[];
    int k20 = blockIdx.x * TILE;
    int t = threadIdx.x;
    int b = t & (TILE - 1), tg = t >> LOG2TILE;    // tg in [0,96)
    float2 x[8], X[8], tw[8];

    // stage 1: radix-8, p=tg
    #pragma unroll
    for (int u = 0; u < 8; u++)
        x[u] = in[(size_t)(tg + 96 * u) * N2V + k20 + b];
    dft8(x, X);
    make_tw8(twid((6.2831853071795865f / 768.0f) * (float)tg), tw);
    #pragma unroll
    for (int r = 0; r < 8; r++)
        bA[EL(8 * tg + r, b)] = (r == 0) ? X[0] : cmul(X[r], tw[r]);
    __syncthreads();

    // stage 2: radix-8, n=96, s=8; q=tg&7, p=tg>>3, in-place
    {
        int q = tg & 7, p = tg >> 3;
        #pragma unroll
        for (int u = 0; u < 8; u++) x[u] = bA[EL(q + 8 * p + 96 * u, b)];
        __syncthreads();
        dft8(x, X);
        make_tw8(twid((6.2831853071795865f / 96.0f) * (float)p), tw);
        #pragma unroll
        for (int r = 0; r < 8; r++)
            bA[EL(q + 64 * p + 8 * r, b)] = (r == 0) ? X[0] : cmul(X[r], tw[r]);
    }
    __syncthreads();

    // stage 3: radix-12, p=0; windowed store + max with interior fast path
    float lmax = 0.0f;
    if (tg < 64) {
        float2 y[12], Y[12];
        int q = tg;
        #pragma unroll
        for (int u = 0; u < 12; u++) y[u] = bA[EL(q + 64 * u, b)];
        dft12(y, Y);
        int kc = k20 + b;
        unsigned wlen = (unsigned)(hi - lo);
        #pragma unroll
        for (int k = 0; k < 12; k++) {
            int k1 = q + 64 * k;
            int m = kc + (k1 << 11);
            int j0 = 2 * m;
            float2 v = make_float2(Y[k].x, -Y[k].y);
            // whole-row interior test: row [2*k1*2048, 2*(k1*2048+2047)+1]
            int rlo = (k1 << 12);              // j0 at kc=0
            if (rlo >= lo && rlo + 4095 < hi) {
                outv[m] = v;
                lmax = fmaxf(lmax, fmaxf(fabsf(v.x), fabsf(v.y)));
            } else {
                if (j0 + 1 >= lo && j0 < hi) outv[m] = v;
                if ((unsigned)(j0     - lo) < wlen) lmax = fmaxf(lmax, fabsf(v.x));
                if ((unsigned)(j0 + 1 - lo) < wlen) lmax = fmaxf(lmax, fabsf(v.y));
            }
        }
    }
    #pragma unroll
    for (int off = 16; off > 0; off >>= 1)
        lmax = fmaxf(lmax, __shfl_xor_sync(0xffffffffu, lmax, off));
    __shared__ float wmax[24];
    int lane = t & 31, w = t >> 5;
    if (lane == 0) wmax[w] = lmax;
    __syncthreads();
    if (t == 0) {
        float mx = wmax[0];
        #pragma unroll
        for (int j = 1; j < 24; j++) mx = fmaxf(mx, wmax[j]);
        atomicMax(&g_max_bits, __float_as_uint(mx));   // values >= 0
    }
}

// ---------------- final: grid-stride float4 normalize
__global__ void final_kernel(const float* __restrict__ yf,
                             float* __restrict__ out, int N, int M) {
    float inv = 1.0f / __uint_as_float(g_max_bits);
    int stride = gridDim.x * blockDim.x;
    for (int i4 = (blockIdx.x * blockDim.x + threadIdx.x) << 2; i4 < N;
         i4 += stride << 2) {
        const float* src = yf + (M - 1) + i4;
        if (i4 + 3 < N) {
            float4 v;
            v.x = src[0] * inv;
            v.y = src[1] * inv;
            v.z = src[2] * inv;
            v.w = src[3] * inv;
            *reinterpret_cast<float4*>(out + i4) = v;
        } else {
            for (int j = 0; i4 + j < N; j++) out[i4 + j] = src[j] * inv;
        }
    }
}

extern "C" void kernel_launch(void* const* d_in, const int* in_sizes, int n_in,
                              void* d_out, int out_size) {
    const float* audio = (const float*)d_in[0];
    const float* ir    = (const float*)d_in[1];
    const int N = in_sizes[0];
    const int M = in_sizes[1];
    float* out = (float*)d_out;

    float2 *A = nullptr, *B = nullptr;
    cudaGetSymbolAddress((void**)&A, g_bufA);
    cudaGetSymbolAddress((void**)&B, g_bufB);

    const int SMEM_R  = SMPAD_R  * (int)sizeof(float2);      // 33792
    const int SMEM_C  = SMPAD_C  * (int)sizeof(float2);      // 50688
    const int SMEM_SI = 2 * SMPAD_R2 * (int)sizeof(float2);  // 33792
    cudaFuncSetAttribute(fwd_cols768,  cudaFuncAttributeMaxDynamicSharedMemorySize, SMEM_C);
    cudaFuncSetAttribute(fwd_rows4096, cudaFuncAttributeMaxDynamicSharedMemorySize, SMEM_R);
    cudaFuncSetAttribute(spec_invrows, cudaFuncAttributeMaxDynamicSharedMemorySize, SMEM_SI);
    cudaFuncSetAttribute(fft_cols768v, cudaFuncAttributeMaxDynamicSharedMemorySize, SMEM_C);

    // forward: cols (direct input, pack fused) -> A (G), rows A -> B (Zrow)
    fwd_cols768<<<N2 / TILE, 384, SMEM_C>>>(audio, N, ir, M, A);
    fwd_rows4096<<<768, 256, SMEM_R>>>(A, B);

    // fused specmul + C2R + inverse row FFTs: B (Zrow) -> A (H)
    spec_invrows<<<384, 256, SMEM_SI>>>(B, A);

    // inverse cols: A -> B (y pairs + fused max)
    fft_cols768v<<<N2V / TILE, 768, SMEM_C>>>(A, B, M - 1, M - 1 + N);

    final_kernel<<<592, 256>>>((const float*)B, out, N, M);
}

// round 17
// speedup vs baseline: 1.0457x; 1.0450x over previous
#include <cuda_runtime.h>

// Reverb via four-step FFT convolution — best-measured composition (R14):
// fwd_cols768 (16/16/3, 384t), fwd_rows4096 (16/16/16, 256t),
// spec_invrows (fused specmul+C2R+2048FFT, 256t), fft_cols768v (8/8/12, 768t),
// final normalize. NFFT = 3*2^20 = 768*4096; NH = 768*2048.

#define NFFT   3145728
#define NH     1572864
#define N2     4096
#define N2V    2048
#define TILE   8
#define LOG2TILE 3
#define SMPAD_R  4224
#define SMPAD_R2 2112
#define SMPAD_C  6336

__device__ float2 g_bufA[1 << 22];
__device__ float2 g_bufB[1 << 22];
__device__ unsigned int g_max_bits;

__device__ __forceinline__ float2 cmul(float2 a, float2 b) {
    return make_float2(fmaf(a.x, b.x, -(a.y * b.y)),
                       fmaf(a.x, b.y,  (a.y * b.x)));
}
__device__ __forceinline__ float2 twid(float ang) {   // e^{-i ang}
    float sn, cs; __sincosf(ang, &sn, &cs);
    return make_float2(cs, -sn);
}
__device__ __forceinline__ int SW(int x) { return x + (x >> 5); }

__device__ __forceinline__ void make_tw8(float2 w1, float2* tw) {
    tw[0] = make_float2(1.0f, 0.0f);
    tw[1] = w1;
    tw[2] = cmul(w1, w1);
    tw[3] = cmul(tw[2], w1);
    tw[4] = cmul(tw[2], tw[2]);
    tw[5] = cmul(tw[4], w1);
    tw[6] = cmul(tw[4], tw[2]);
    tw[7] = cmul(tw[4], tw[3]);
}
__device__ __forceinline__ void make_tw16(float2 w1, float2* tw) {
    tw[0] = make_float2(1.0f, 0.0f);
    tw[1] = w1;
    tw[2] = cmul(w1, w1);
    tw[3] = cmul(tw[2], w1);
    tw[4] = cmul(tw[2], tw[2]);
    tw[8] = cmul(tw[4], tw[4]);
    tw[12] = cmul(tw[8], tw[4]);
    tw[5]  = cmul(tw[4],  w1);
    tw[6]  = cmul(tw[4],  tw[2]);
    tw[7]  = cmul(tw[4],  tw[3]);
    tw[9]  = cmul(tw[8],  w1);
    tw[10] = cmul(tw[8],  tw[2]);
    tw[11] = cmul(tw[8],  tw[3]);
    tw[13] = cmul(tw[12], w1);
    tw[14] = cmul(tw[12], tw[2]);
    tw[15] = cmul(tw[12], tw[3]);
}

__device__ __forceinline__ void r4core(float2 a, float2 b, float2 c, float2 d,
                                       float2& e0, float2& e1, float2& e2, float2& e3) {
    float2 apc = make_float2(a.x + c.x, a.y + c.y);
    float2 amc = make_float2(a.x - c.x, a.y - c.y);
    float2 bpd = make_float2(b.x + d.x, b.y + d.y);
    float2 bmd = make_float2(b.x - d.x, b.y - d.y);
    e0 = make_float2(apc.x + bpd.x, apc.y + bpd.y);
    e1 = make_float2(amc.x + bmd.y, amc.y - bmd.x);
    e2 = make_float2(apc.x - bpd.x, apc.y - bpd.y);
    e3 = make_float2(amc.x - bmd.y, amc.y + bmd.x);
}

__device__ __forceinline__ void dft8(const float2* x, float2* X) {
    const float R2 = 0.70710678118654752440f;
    float2 E0, E1, E2, E3, O0, O1, O2, O3;
    r4core(x[0], x[2], x[4], x[6], E0, E1, E2, E3);
    r4core(x[1], x[3], x[5], x[7], O0, O1, O2, O3);
    float2 T1 = cmul(O1, make_float2( R2, -R2));
    float2 T2 = make_float2(O2.y, -O2.x);
    float2 T3 = cmul(O3, make_float2(-R2, -R2));
    X[0] = make_float2(E0.x + O0.x, E0.y + O0.y);
    X[4] = make_float2(E0.x - O0.x, E0.y - O0.y);
    X[1] = make_float2(E1.x + T1.x, E1.y + T1.y);
    X[5] = make_float2(E1.x - T1.x, E1.y - T1.y);
    X[2] = make_float2(E2.x + T2.x, E2.y + T2.y);
    X[6] = make_float2(E2.x - T2.x, E2.y - T2.y);
    X[3] = make_float2(E3.x + T3.x, E3.y + T3.y);
    X[7] = make_float2(E3.x - T3.x, E3.y - T3.y);
}

__device__ __forceinline__ void dft16(const float2* x, float2* X) {
    const float C1 = 0.92387953251128675613f;
    const float S1 = 0.38268343236508977173f;
    const float R2 = 0.70710678118654752440f;
    float2 t0[4], t1[4], t2[4], t3[4];
    r4core(x[0], x[4], x[8],  x[12], t0[0], t0[1], t0[2], t0[3]);
    r4core(x[1], x[5], x[9],  x[13], t1[0], t1[1], t1[2], t1[3]);
    r4core(x[2], x[6], x[10], x[14], t2[0], t2[1], t2[2], t2[3]);
    r4core(x[3], x[7], x[11], x[15], t3[0], t3[1], t3[2], t3[3]);
    t1[1] = cmul(t1[1], make_float2( C1, -S1));
    t1[2] = cmul(t1[2], make_float2( R2, -R2));
    t1[3] = cmul(t1[3], make_float2( S1, -C1));
    t2[1] = cmul(t2[1], make_float2( R2, -R2));
    t2[2] = make_float2(t2[2].y, -t2[2].x);
    t2[3] = cmul(t2[3], make_float2(-R2, -R2));
    t3[1] = cmul(t3[1], make_float2( S1, -C1));
    t3[2] = cmul(t3[2], make_float2(-R2, -R2));
    t3[3] = cmul(t3[3], make_float2(-C1,  S1));
    r4core(t0[0], t1[0], t2[0], t3[0], X[0], X[4], X[8],  X[12]);
    r4core(t0[1], t1[1], t2[1], t3[1], X[1], X[5], X[9],  X[13]);
    r4core(t0[2], t1[2], t2[2], t3[2], X[2], X[6], X[10], X[14]);
    r4core(t0[3], t1[3], t2[3], t3[3], X[3], X[7], X[11], X[15]);
}

// 12-point DFT, natural-order output.
__device__ __forceinline__ void dft12(const float2* x, float2* X) {
    const float SQ32 = 0.86602540378443864676f;
    float2 T[4][3];
    #pragma unroll
    for (int r = 0; r < 4; r++) {
        float2 a = x[r], b = x[4 + r], c = x[8 + r];
        float2 t = make_float2(b.x + c.x, b.y + c.y);
        float2 u = make_float2(b.x - c.x, b.y - c.y);
        T[r][0] = make_float2(a.x + t.x, a.y + t.y);
        float rx = a.x - 0.5f * t.x, ry = a.y - 0.5f * t.y;
        T[r][1] = make_float2(rx + SQ32 * u.y, ry - SQ32 * u.x);
        T[r][2] = make_float2(rx - SQ32 * u.y, ry + SQ32 * u.x);
    }
    const float2 W1 = make_float2( SQ32, -0.5f );
    const float2 W2 = make_float2( 0.5f, -SQ32 );
    const float2 W4 = make_float2(-0.5f, -SQ32 );
    T[1][1] = cmul(T[1][1], W1);
    T[1][2] = cmul(T[1][2], W2);
    T[2][1] = cmul(T[2][1], W2);
    T[2][2] = cmul(T[2][2], W4);
    T[3][1] = make_float2(T[3][1].y, -T[3][1].x);
    T[3][2] = make_float2(-T[3][2].x, -T[3][2].y);
    #pragma unroll
    for (int k1 = 0; k1 < 3; k1++)
        r4core(T[0][k1], T[1][k1], T[2][k1], T[3][k1],
               X[k1], X[k1 + 3], X[k1 + 6], X[k1 + 9]);
}

__device__ __forceinline__ float2 unpackY(float2 zk, float2 zn) {
    float2 A  = make_float2(0.5f * (zk.x + zn.x), 0.5f * (zk.y - zn.y));
    float2 Dv = make_float2(zk.x - zn.x, zk.y + zn.y);
    float2 H  = make_float2(0.5f * Dv.y, -0.5f * Dv.x);
    return cmul(A, H);
}

__device__ __forceinline__ void c2rsplit(float2 Ym, float2 Yc, float th,
                                         float2& wm, float2& wmir) {
    float2 E = make_float2(0.5f * (Ym.x + Yc.x), 0.5f * (Ym.y - Yc.y));
    float2 G = make_float2(0.5f * (Ym.x - Yc.x), 0.5f * (Ym.y + Yc.y));
    float sn, cs; __sincosf(th, &sn, &cs);
    float2 O = cmul(make_float2(cs, sn), G);
    wm   = make_float2(E.x - O.y, -E.y - O.x);
    wmir = make_float2(E.x + O.y,  E.y - O.x);
}

#define EL(idx, b) SW((((idx) << LOG2TILE)) + (b))

// ---------------- fwd_cols768: radices 16/16/3, 384 threads, TILE=8
__global__ void fwd_cols768(const float* __restrict__ audio, int N,
                            const float* __restrict__ ir, int M,
                            float2* __restrict__ G) {
    extern __shared__ float2 bA[];
    int k20 = blockIdx.x * TILE;
    int t = threadIdx.x;
    int b = t & (TILE - 1), tt = t >> LOG2TILE;    // tt in [0,48)
    if (blockIdx.x == 0 && t == 0) g_max_bits = 0u;
    float2 x[16], X[16], tw[16];

    #pragma unroll
    for (int u = 0; u < 16; u++) {
        int n = (tt + 48 * u) * 4096 + k20 + b;
        float re = (n < N) ? audio[n] : 0.0f;
        float im = (n < M) ? ir[M - 1 - n] : 0.0f;
        x[u] = make_float2(re, im);
    }
    dft16(x, X);
    make_tw16(twid((6.2831853071795865f / 768.0f) * (float)tt), tw);
    #pragma unroll
    for (int r = 0; r < 16; r++)
        bA[SW(((16 * tt + r) << LOG2TILE) + b)] = (r == 0) ? X[0] : cmul(X[r], tw[r]);
    __syncthreads();

    #pragma unroll
    for (int u = 0; u < 16; u++) x[u] = bA[SW(((tt + 48 * u) << LOG2TILE) + b)];
    __syncthreads();
    dft16(x, X);
    {
        int q = tt & 15, p = tt >> 4;
        make_tw16(twid((6.2831853071795865f / 48.0f) * (float)p), tw);
        int base = q + (p << 8);
        #pragma unroll
        for (int r = 0; r < 16; r++)
            bA[SW(((base + 16 * r) << LOG2TILE) + b)] = (r == 0) ? X[0] : cmul(X[r], tw[r]);
    }
    __syncthreads();

    const float SQ32 = 0.86602540378443864676f;
    const float c0 = 6.2831853071795865f / (float)NFFT;
    int kc = k20 + b;
    float2 cur = twid(c0 * (float)(kc * tt));
    float2 S   = twid(c0 * (float)(kc * 48));
    float2 P1  = twid(c0 * (float)(kc * 256));
    float2 P2  = cmul(P1, P1);
    for (int q = tt; q < 256; q += 48) {
        float2 a  = bA[SW(((q      ) << LOG2TILE) + b)];
        float2 bb = bA[SW(((q + 256) << LOG2TILE) + b)];
        float2 c  = bA[SW(((q + 512) << LOG2TILE) + b)];
        float2 ts = make_float2(bb.x + c.x, bb.y + c.y);
        float2 u  = make_float2(bb.x - c.x, bb.y - c.y);
        float2 e0 = make_float2(a.x + ts.x, a.y + ts.y);
        float rx = a.x - 0.5f * ts.x, ry = a.y - 0.5f * ts.y;
        float2 e1 = make_float2(rx + SQ32 * u.y, ry - SQ32 * u.x);
        float2 e2 = make_float2(rx - SQ32 * u.y, ry + SQ32 * u.x);
        G[(size_t)(q      ) * N2 + kc] = cmul(e0, cur);
        G[(size_t)(q + 256) * N2 + kc] = cmul(e1, cmul(cur, P1));
        G[(size_t)(q + 512) * N2 + kc] = cmul(e2, cmul(cur, P2));
        cur = cmul(cur, S);
    }
}

// ---------------- fwd_rows4096
__global__ void fwd_rows4096(const float2* __restrict__ in, float2* __restrict__ out) {
    extern __shared__ float2 bA[];
    int t = threadIdx.x;
    const float2* row = in + (size_t)blockIdx.x * N2;
    float2* orow = out + (size_t)blockIdx.x * N2;
    float2 x[16], X[16], tw[16];

    #pragma unroll
    for (int u = 0; u < 16; u++) x[u] = row[t + (u << 8)];
    dft16(x, X);
    make_tw16(twid((6.2831853071795865f / 4096.0f) * (float)t), tw);
    #pragma unroll
    for (int r = 0; r < 16; r++)
        bA[SW(16 * t + r)] = (r == 0) ? X[0] : cmul(X[r], tw[r]);
    __syncthreads();

    #pragma unroll
    for (int u = 0; u < 16; u++) x[u] = bA[SW(t + (u << 8))];
    __syncthreads();
    dft16(x, X);
    {
        int q = t & 15, p = t >> 4;
        make_tw16(twid((6.2831853071795865f / 256.0f) * (float)p), tw);
        int base = q + (p << 8);
        #pragma unroll
        for (int r = 0; r < 16; r++)
            bA[SW(base + 16 * r)] = (r == 0) ? X[0] : cmul(X[r], tw[r]);
    }
    __syncthreads();

    #pragma unroll
    for (int u = 0; u < 16; u++) x[u] = bA[SW(t + (u << 8))];
    dft16(x, X);
    #pragma unroll
    for (int r = 0; r < 16; r++) orow[t + (r << 8)] = X[r];
}

// ---------------- spec_invrows: 256 threads, two 128-thr groups
__global__ void spec_invrows(const float2* __restrict__ Zr, float2* __restrict__ H) {
    extern __shared__ float2 sm[];
    float2* win[2] = { sm, sm + SMPAD_R2 };
    int t = threadIdx.x;
    int r = blockIdx.x;
    const float c1 = 6.2831853071795865f / (float)NFFT;

    int row0, row1;
    if (r == 0) {
        row0 = 0; row1 = 384;
        #pragma unroll
        for (int j = 0; j < 4; j++) {
            int c = 1 + t + (j << 8);          // [1,1024]
            float2 Ym = unpackY(Zr[c], Zr[4096 - c]);
            float2 Yc = unpackY(Zr[2048 - c], Zr[2048 + c]);
            float2 wm, wmir;
            c2rsplit(Ym, Yc, c1 * (float)(768 * c), wm, wmir);
            win[0][SW(c)] = wm;
            win[0][SW(2048 - c)] = wmir;
        }
        const size_t base = (size_t)384 * N2;
        #pragma unroll
        for (int j = 0; j < 4; j++) {
            int c = t + (j << 8);              // [0,1023]
            float2 Ym = unpackY(Zr[base + c], Zr[base + 4095 - c]);
            float2 Yc = unpackY(Zr[base + 2047 - c], Zr[base + 2048 + c]);
            float2 wm, wmir;
            c2rsplit(Ym, Yc, c1 * (float)(384 + 768 * c), wm, wmir);
            win[1][SW(c)] = wm;
            win[1][SW(2047 - c)] = wmir;
        }
        if (t == 0) {
            float2 z0 = Zr[0], zh = Zr[2048];
            float Y0 = z0.x * z0.y;
            float Yh = zh.x * zh.y;
            win[0][SW(0)] = make_float2(0.5f * (Y0 + Yh), -0.5f * (Y0 - Yh));
        }
    } else {
        row0 = r; row1 = 768 - r;
        const size_t bR = (size_t)r * N2;
        const size_t bM = (size_t)(768 - r) * N2;
        #pragma unroll
        for (int j = 0; j < 8; j++) {
            int c = t + (j << 8);              // [0,2048)
            float2 Ym = unpackY(Zr[bR + c],        Zr[bM + 4095 - c]);
            float2 Yc = unpackY(Zr[bM + 2047 - c], Zr[bR + 2048 + c]);
            float2 wm, wmir;
            c2rsplit(Ym, Yc, c1 * (float)(r + 768 * c), wm, wmir);
            win[0][SW(c)] = wm;
            win[1][SW(2047 - c)] = wmir;
        }
    }
    __syncthreads();

    int g = t >> 7;
    int tl = t & 127;
    int n1 = g ? row1 : row0;
    float2* wi = win[g];
    float2* orow = H + (size_t)n1 * N2V;
    float2 x[16], X[16], tw[16];

    #pragma unroll
    for (int u = 0; u < 16; u++) x[u] = wi[SW(tl + (u << 7))];
    __syncthreads();
    dft16(x, X);
    make_tw16(twid((6.2831853071795865f / 2048.0f) * (float)tl), tw);
    #pragma unroll
    for (int rr = 0; rr < 16; rr++)
        wi[SW(16 * tl + rr)] = (rr == 0) ? X[0] : cmul(X[rr], tw[rr]);
    __syncthreads();

    #pragma unroll
    for (int u = 0; u < 16; u++) x[u] = wi[SW(tl + (u << 7))];
    __syncthreads();
    dft16(x, X);
    {
        int q = tl & 15, p = tl >> 4;
        make_tw16(twid((6.2831853071795865f / 128.0f) * (float)p), tw);
        int base = q + (p << 8);
        #pragma unroll
        for (int rr = 0; rr < 16; rr++)
            wi[SW(base + 16 * rr)] = (rr == 0) ? X[0] : cmul(X[rr], tw[rr]);
    }
    __syncthreads();

    {
        const float c0 = 6.2831853071795865f / (float)NH;
        float2 y[8], Y8[8];
        #pragma unroll
        for (int qq0 = 0; qq0 < 2; qq0++) {
            int q = tl + (qq0 << 7);
            #pragma unroll
            for (int u = 0; u < 8; u++) y[u] = wi[SW(q + (u << 8))];
            dft8(y, Y8);
            float2 V  = twid(c0 * (float)(n1 << 8));
            float2 V2 = cmul(V, V);
            float2 V4 = cmul(V2, V2);
            float2 base0 = twid(c0 * (float)(n1 * q));
            float2 vv[8];
            vv[0] = base0;
            vv[1] = cmul(base0, V);
            vv[2] = cmul(base0, V2);
            vv[3] = cmul(vv[2], V);
            vv[4] = cmul(base0, V4);
            vv[5] = cmul(vv[4], V);
            vv[6] = cmul(vv[4], V2);
            vv[7] = cmul(vv[6], V);
            #pragma unroll
            for (int rr = 0; rr < 8; rr++) orow[q + (rr << 8)] = cmul(Y8[rr], vv[rr]);
        }
    }
}

// ---------------- fft_cols768v: radices (8,8,12), 768 threads, TILE=8
__global__ void fft_cols768v(const float2* __restrict__ in, float2* __restrict__ outv,
                             int lo, int hi) {
    extern __shared__ float2 bA[];
    int k20 = blockIdx.x * TILE;
    int t = threadIdx.x;
    int b = t & (TILE - 1), tg = t >> LOG2TILE;    // tg in [0,96)
    float2 x[8], X[8], tw[8];

    // stage 1: radix-8, p=tg
    #pragma unroll
    for (int u = 0; u < 8; u++)
        x[u] = in[(size_t)(tg + 96 * u) * N2V + k20 + b];
    dft8(x, X);
    make_tw8(twid((6.2831853071795865f / 768.0f) * (float)tg), tw);
    #pragma unroll
    for (int r = 0; r < 8; r++)
        bA[EL(8 * tg + r, b)] = (r == 0) ? X[0] : cmul(X[r], tw[r]);
    __syncthreads();

    // stage 2: radix-8, n=96, s=8; q=tg&7, p=tg>>3, in-place
    {
        int q = tg & 7, p = tg >> 3;
        #pragma unroll
        for (int u = 0; u < 8; u++) x[u] = bA[EL(q + 8 * p + 96 * u, b)];
        __syncthreads();
        dft8(x, X);
        make_tw8(twid((6.2831853071795865f / 96.0f) * (float)p), tw);
        #pragma unroll
        for (int r = 0; r < 8; r++)
            bA[EL(q + 64 * p + 8 * r, b)] = (r == 0) ? X[0] : cmul(X[r], tw[r]);
    }
    __syncthreads();

    // stage 3: radix-12, p=0; windowed real output + max
    float lmax = 0.0f;
    if (tg < 64) {
        float2 y[12], Y[12];
        int q = tg;
        #pragma unroll
        for (int u = 0; u < 12; u++) y[u] = bA[EL(q + 64 * u, b)];
        dft12(y, Y);
        int kc = k20 + b;
        unsigned wlen = (unsigned)(hi - lo);
        #pragma unroll
        for (int k = 0; k < 12; k++) {
            int k1 = q + 64 * k;
            int m = kc + (k1 << 11);
            int j0 = 2 * m;
            float2 v = make_float2(Y[k].x, -Y[k].y);
            if (j0 + 1 >= lo && j0 < hi) outv[m] = v;
            if ((unsigned)(j0     - lo) < wlen) lmax = fmaxf(lmax, fabsf(v.x));
            if ((unsigned)(j0 + 1 - lo) < wlen) lmax = fmaxf(lmax, fabsf(v.y));
        }
    }
    #pragma unroll
    for (int off = 16; off > 0; off >>= 1)
        lmax = fmaxf(lmax, __shfl_xor_sync(0xffffffffu, lmax, off));
    __shared__ float wmax[24];
    int lane = t & 31, w = t >> 5;
    if (lane == 0) wmax[w] = lmax;
    __syncthreads();
    if (t == 0) {
        float mx = wmax[0];
        #pragma unroll
        for (int j = 1; j < 24; j++) mx = fmaxf(mx, wmax[j]);
        atomicMax(&g_max_bits, __float_as_uint(mx));   // values >= 0
    }
}

// ---------------- final: out[i] = y[M-1+i] * (1/max), float4 stores
__global__ void final_kernel(const float* __restrict__ yf,
                             float* __restrict__ out, int N, int M) {
    int i4 = (blockIdx.x * blockDim.x + threadIdx.x) << 2;
    if (i4 >= N) return;
    float inv = 1.0f / __uint_as_float(g_max_bits);
    const float* src = yf + (M - 1) + i4;
    if (i4 + 3 < N) {
        float4 v;
        v.x = src[0] * inv;
        v.y = src[1] * inv;
        v.z = src[2] * inv;
        v.w = src[3] * inv;
        *reinterpret_cast<float4*>(out + i4) = v;
    } else {
        for (int j = 0; i4 + j < N; j++) out[i4 + j] = src[j] * inv;
    }
}

extern "C" void kernel_launch(void* const* d_in, const int* in_sizes, int n_in,
                              void* d_out, int out_size) {
    const float* audio = (const float*)d_in[0];
    const float* ir    = (const float*)d_in[1];
    const int N = in_sizes[0];
    const int M = in_sizes[1];
    float* out = (float*)d_out;

    float2 *A = nullptr, *B = nullptr;
    cudaGetSymbolAddress((void**)&A, g_bufA);
    cudaGetSymbolAddress((void**)&B, g_bufB);

    const int SMEM_R  = SMPAD_R  * (int)sizeof(float2);      // 33792
    const int SMEM_C  = SMPAD_C  * (int)sizeof(float2);      // 50688
    const int SMEM_SI = 2 * SMPAD_R2 * (int)sizeof(float2);  // 33792
    cudaFuncSetAttribute(fwd_cols768,  cudaFuncAttributeMaxDynamicSharedMemorySize, SMEM_C);
    cudaFuncSetAttribute(fwd_rows4096, cudaFuncAttributeMaxDynamicSharedMemorySize, SMEM_R);
    cudaFuncSetAttribute(spec_invrows, cudaFuncAttributeMaxDynamicSharedMemorySize, SMEM_SI);
    cudaFuncSetAttribute(fft_cols768v, cudaFuncAttributeMaxDynamicSharedMemorySize, SMEM_C);

    // forward: cols (direct input, pack fused) -> A (G), rows A -> B (Zrow)
    fwd_cols768<<<N2 / TILE, 384, SMEM_C>>>(audio, N, ir, M, A);
    fwd_rows4096<<<768, 256, SMEM_R>>>(A, B);

    // fused specmul + C2R + inverse row FFTs: B (Zrow) -> A (H)
    spec_invrows<<<384, 256, SMEM_SI>>>(B, A);

    // inverse cols: A -> B (y pairs + fused max)
    fft_cols768v<<<N2V / TILE, 768, SMEM_C>>>(A, B, M - 1, M - 1 + N);

    final_kernel<<<(N / 4 + 255) / 256, 256>>>((const float*)B, out, N, M);
}